// round 8
// baseline (speedup 1.0000x reference)
#include <cuda_runtime.h>

#define T_STEPS 2048
#define BATCH   2048
#define HID     32

#define NB   7      // batches per team
#define NBP  8      // padded batch dim in smem

typedef unsigned long long u64;

#define S_SIG  (-1.4426950408889634f)   /* -log2(e)   */
#define S_TNH  (-2.8853900817779268f)   /* -2*log2(e) */

// ---- packed f32x2 helpers ----
__device__ __forceinline__ u64 ffma2(u64 a, u64 b, u64 c) {
    u64 d;
    asm("fma.rn.f32x2 %0, %1, %2, %3;" : "=l"(d) : "l"(a), "l"(b), "l"(c));
    return d;
}
__device__ __forceinline__ u64 pack2(float lo, float hi) {
    u64 d;
    asm("mov.b64 %0, {%1, %2};" : "=l"(d) : "f"(lo), "f"(hi));
    return d;
}
__device__ __forceinline__ void unpack2(u64 v, float& lo, float& hi) {
    asm("mov.b64 {%0, %1}, %2;" : "=f"(lo), "=f"(hi) : "l"(v));
}
__device__ __forceinline__ float ex2f(float x) {
    float y; asm("ex2.approx.f32 %0, %1;" : "=f"(y) : "f"(x)); return y;
}
__device__ __forceinline__ float rcpf(float x) {
    float y; asm("rcp.approx.f32 %0, %1;" : "=f"(y) : "f"(x)); return y;
}
__device__ __forceinline__ void stg32_pred(int pred, float* p, float a) {
    asm volatile("{\n\t"
                 ".reg .pred p;\n\t"
                 "setp.ne.u32 p, %0, 0;\n\t"
                 "@p st.global.f32 [%1], %2;\n\t"
                 "}" :: "r"(pred), "l"(p), "f"(a) : "memory");
}
__device__ __forceinline__ void team_bar(int team) {
    asm volatile("bar.sync %0, %1;" :: "r"(1 + team), "r"(128) : "memory");
}

__global__ void __launch_bounds__(256, 1) lstm_kernel(
    const float* __restrict__ x,      // [T, B, 1]
    const float* __restrict__ W_ih,   // [4H, 1]
    const float* __restrict__ W_hh,   // [4H, H]
    const float* __restrict__ b_ih,   // [4H]
    const float* __restrict__ b_hh,   // [4H]
    const float* __restrict__ W_out,  // [1, H]
    const float* __restrict__ b_out,  // [1]
    float* __restrict__ out,          // [T*B] outs, then [B*H] hT, then [B*H] cT
    int out_size)
{
    const int lane = threadIdx.x & 31;
    const int wid  = threadIdx.x >> 5;
    const int gate = wid & 3;                 // warp owns one gate (i,f,g,o)
    const int team = wid >> 2;                // 2 teams per CTA
    const int gteam = blockIdx.x * 2 + team;  // 0..295
    const int b0 = gteam * NB;                // team's first global batch

    // Own gate's weight rows, pre-scaled (i,f,o: S_SIG; g: S_TNH)
    const float s = (gate == 2) ? S_TNH : S_SIG;
    const int row = gate * 32 + lane;
    u64 w2[16];
    {
        const float* wr = W_hh + row * HID;
        #pragma unroll
        for (int p = 0; p < 16; p++)
            w2[p] = pack2(wr[2 * p] * s, wr[2 * p + 1] * s);
    }
    const float wih  = W_ih[row] * s;
    const float bias = (b_ih[row] + b_hh[row]) * s;
    const float wout = W_out[lane];
    const float bout = b_out[0];

    // smem: h per team-batch (single buffer; barriers order access), activated gates
    __shared__ __align__(16) float hbuf[2][NBP][32];
    __shared__ __align__(16) float gact[2][4][NBP][32];

    // zero smem (pad rows must be 0 so gate-3's dummy pair stays 0)
    {
        float* sm = &hbuf[0][0][0];
        for (int i = threadIdx.x; i < 2 * NBP * 32; i += 256) sm[i] = 0.f;
        float* ga = &gact[0][0][0][0];
        for (int i = threadIdx.x; i < 2 * 4 * NBP * 32; i += 256) ga[i] = 0.f;
    }
    __syncthreads();

    // combine assignment: warp `gate` updates c/h for team batches 2g, 2g+1
    const int mb0 = 2 * gate;
    const int mb1 = 2 * gate + 1;             // ==7 (pad) for gate 3
    const bool two = (gate < 3);
    const int bg0 = b0 + mb0;
    const int bg1 = b0 + mb1;
    const int pred0 = (lane == 0) && (bg0 < BATCH);
    const int pred1 = (lane == 0) && two && (bg1 < BATCH);

    // clamped x offsets for this team's batches
    int xoff[NB];
    #pragma unroll
    for (int b = 0; b < NB; b++) {
        int bg = b0 + b;
        xoff[b] = (bg < BATCH) ? bg : (BATCH - 1);
    }

    float c0 = 0.f, c1 = 0.f, h0 = 0.f, h1 = 0.f;
    float rp0 = 0.f, rp1 = 0.f;               // deferred output partials

    // prefetch x for t=0
    const float* xrow = x;
    float xr[NB];
    #pragma unroll
    for (int b = 0; b < NB; b++) xr[b] = __ldg(xrow + xoff[b]);

    float* orow = out;                        // row being stored (t-1), advanced per step

    #pragma unroll 1
    for (int t = 0; t < T_STEPS; t++) {
        // ---- init accumulators with x/bias contribution ----
        u64 acc[NB];
        #pragma unroll
        for (int b = 0; b < NB; b++)
            acc[b] = pack2(fmaf(xr[b], wih, bias), 0.f);

        // ---- deferred reduction of step t-1 output partials (hidden under matvec) ----
        float r0 = rp0, r1 = rp1;
        #pragma unroll
        for (int off = 16; off; off >>= 1) {
            r0 += __shfl_xor_sync(0xffffffffu, r0, off);
            r1 += __shfl_xor_sync(0xffffffffu, r1, off);
        }

        // ---- matvec: 7 batches x 16 FFMA2 (own gate only) ----
        #pragma unroll
        for (int b = 0; b < NB; b++) {
            const double2* hb = reinterpret_cast<const double2*>(hbuf[team][b]);
            #pragma unroll
            for (int q = 0; q < 8; q++) {
                double2 v = hb[q];
                acc[b] = ffma2(__double_as_longlong(v.x), w2[2 * q],     acc[b]);
                acc[b] = ffma2(__double_as_longlong(v.y), w2[2 * q + 1], acc[b]);
            }
        }

        // ---- store out[t-1] (placeholder at t==0, overwritten at t==1) ----
        stg32_pred(pred0, orow + bg0, r0 + bout);
        stg32_pred(pred1, orow + bg1, r1 + bout);
        orow += (t > 0) ? BATCH : 0;

        // ---- prefetch next x ----
        const float* xn = (t < T_STEPS - 1) ? (xrow + BATCH) : xrow;
        xrow = xn;
        #pragma unroll
        for (int b = 0; b < NB; b++) xr[b] = __ldg(xn + xoff[b]);

        // ---- activations for own gate, shared-rcp in groups of 4+3 ----
        float P[NB];
        #pragma unroll
        for (int b = 0; b < NB; b++) {
            float lo, hi;
            unpack2(acc[b], lo, hi);
            P[b] = 1.f + ex2f(lo + hi);
        }
        float inv[NB];
        {
            float P01 = P[0] * P[1], P23 = P[2] * P[3];
            float R = rcpf(P01 * P23);
            inv[0] = P[1] * P23 * R;
            inv[1] = P[0] * P23 * R;
            inv[2] = P01 * P[3] * R;
            inv[3] = P01 * P[2] * R;
        }
        {
            float P45 = P[4] * P[5], P56 = P[5] * P[6];
            float R = rcpf(P45 * P[6]);
            inv[4] = P56 * R;
            inv[5] = P[4] * P[6] * R;
            inv[6] = P45 * R;
        }
        // sigmoid gates use inv directly; tanh gate (gate==2) maps to 2*inv-1
        if (gate == 2) {
            #pragma unroll
            for (int b = 0; b < NB; b++)
                gact[team][2][b][lane] = fmaf(2.f, inv[b], -1.f);
        } else {
            #pragma unroll
            for (int b = 0; b < NB; b++)
                gact[team][gate][b][lane] = inv[b];
        }

        team_bar(team);

        // ---- combine: update c/h for my 2 batches ----
        float ia0 = gact[team][0][mb0][lane];
        float fa0 = gact[team][1][mb0][lane];
        float ga0 = gact[team][2][mb0][lane];
        float oa0 = gact[team][3][mb0][lane];
        float ia1 = gact[team][0][mb1][lane];   // pad row -> 0 for gate 3
        float fa1 = gact[team][1][mb1][lane];
        float ga1 = gact[team][2][mb1][lane];
        float oa1 = gact[team][3][mb1][lane];

        c0 = fmaf(fa0, c0, ia0 * ga0);
        c1 = fmaf(fa1, c1, ia1 * ga1);

        {   // paired tanh(c): one rcp for both batches
            float a0 = fminf(c0 * S_TNH, 63.f);
            float a1 = fminf(c1 * S_TNH, 63.f);
            float T0 = 1.f + ex2f(a0);
            float T1 = 1.f + ex2f(a1);
            float Rt = rcpf(T0 * T1);
            h0 = oa0 * fmaf(2.f, T1 * Rt, -1.f);
            h1 = oa1 * fmaf(2.f, T0 * Rt, -1.f);
        }

        hbuf[team][mb0][lane] = h0;
        hbuf[team][mb1][lane] = h1;            // gate3 writes pad (h1==0, harmless)

        rp0 = h0 * wout;
        rp1 = h1 * wout;

        team_bar(team);
    }

    // epilogue: out[T-1] (orow already points at row T-1)
    {
        float r0 = rp0, r1 = rp1;
        #pragma unroll
        for (int off = 16; off; off >>= 1) {
            r0 += __shfl_xor_sync(0xffffffffu, r0, off);
            r1 += __shfl_xor_sync(0xffffffffu, r1, off);
        }
        stg32_pred(pred0, orow + bg0, r0 + bout);
        stg32_pred(pred1, orow + bg1, r1 + bout);
    }

    // final state (hT, cT)
    if (out_size >= T_STEPS * BATCH + 2 * BATCH * HID) {
        float* hT = out + (size_t)T_STEPS * BATCH;
        float* cT = hT + BATCH * HID;
        if (bg0 < BATCH) {
            hT[(size_t)bg0 * HID + lane] = h0;
            cT[(size_t)bg0 * HID + lane] = c0;
        }
        if (two && bg1 < BATCH) {
            hT[(size_t)bg1 * HID + lane] = h1;
            cT[(size_t)bg1 * HID + lane] = c1;
        }
    }
}

extern "C" void kernel_launch(void* const* d_in, const int* in_sizes, int n_in,
                              void* d_out, int out_size) {
    const float* x     = (const float*)d_in[0];
    const float* W_ih  = (const float*)d_in[1];
    const float* W_hh  = (const float*)d_in[2];
    const float* b_ih  = (const float*)d_in[3];
    const float* b_hh  = (const float*)d_in[4];
    const float* W_out = (const float*)d_in[5];
    const float* b_out = (const float*)d_in[6];
    float* out = (float*)d_out;

    // 148 CTAs x 256 threads: 2 gate-parallel teams per CTA, 7 batches per team,
    // 296 teams covering 2048 batches (24 masked dummies). All 148 SMs, 2 warps/SMSP.
    lstm_kernel<<<148, 256>>>(x, W_ih, W_hh, b_ih, b_hh, W_out, b_out, out, out_size);
}

// round 11
// speedup vs baseline: 1.1841x; 1.1841x over previous
#include <cuda_runtime.h>

#define T_STEPS 2048
#define BATCH   2048
#define HID     32

typedef unsigned long long u64;

#define S_SIG  (-1.4426950408889634f)   /* -log2(e)   */
#define S_TNH  (-2.8853900817779268f)   /* -2*log2(e) */

// ---- packed f32x2 helpers ----
__device__ __forceinline__ u64 ffma2(u64 a, u64 b, u64 c) {
    u64 d;
    asm("fma.rn.f32x2 %0, %1, %2, %3;" : "=l"(d) : "l"(a), "l"(b), "l"(c));
    return d;
}
__device__ __forceinline__ u64 pack2(float lo, float hi) {
    u64 d;
    asm("mov.b64 %0, {%1, %2};" : "=l"(d) : "f"(lo), "f"(hi));
    return d;
}
__device__ __forceinline__ void unpack2(u64 v, float& lo, float& hi) {
    asm("mov.b64 {%0, %1}, %2;" : "=f"(lo), "=f"(hi) : "l"(v));
}
__device__ __forceinline__ float ex2f(float x) {
    float y; asm("ex2.approx.f32 %0, %1;" : "=f"(y) : "f"(x)); return y;
}
__device__ __forceinline__ float rcpf(float x) {
    float y; asm("rcp.approx.f32 %0, %1;" : "=f"(y) : "f"(x)); return y;
}
__device__ __forceinline__ void stg64_pred(int pred, float* p, float a, float b) {
    asm volatile("{\n\t"
                 ".reg .pred p;\n\t"
                 "setp.ne.u32 p, %0, 0;\n\t"
                 "@p st.global.v2.f32 [%1], {%2, %3};\n\t"
                 "}" :: "r"(pred), "l"(p), "f"(a), "f"(b) : "memory");
}

// single-batch LSTM activation block: gates (quad-shared rcp) + c/h update
__device__ __forceinline__ void act_one(const u64 acc[4], float& c, float& h,
                                        float& rp, const float wout) {
    float vi, vf, vg, vo;
    {
        float lo, hi;
        unpack2(acc[0], lo, hi); vi = lo + hi;
        unpack2(acc[1], lo, hi); vf = lo + hi;
        unpack2(acc[2], lo, hi); vg = lo + hi;
        unpack2(acc[3], lo, hi); vo = lo + hi;
    }
    float Ei = ex2f(vi), Ef = ex2f(vf), Eg = ex2f(vg), Eo = ex2f(vo);
    float Pi = 1.f + Ei, Pf = 1.f + Ef, Pg = 1.f + Eg, Po = 1.f + Eo;
    float Pif = Pi * Pf, Pgo = Pg * Po;
    float R = rcpf(Pif * Pgo);
    float PgoR = Pgo * R, PifR = Pif * R;
    float ig = Pf * PgoR;                  // sigmoid(i)
    float fg = Pi * PgoR;                  // sigmoid(f)
    float og = PifR * Pg;                  // sigmoid(o)
    float gg = fmaf(2.f, PifR * Po, -1.f); // tanh(g)
    c = fmaf(fg, c, ig * gg);
    float a = fminf(c * S_TNH, 63.f);
    float T = 1.f + ex2f(a);
    h = og * fmaf(2.f, rcpf(T), -1.f);
    rp = h * wout;
}

// 64-FFMA2 recurrent matvec for one batch (all 4 gates), h read from smem
__device__ __forceinline__ void matvec_one(u64 acc[4], const float* hs,
                                           const u64 w2[4][16]) {
    const double2* hp = reinterpret_cast<const double2*>(hs);
    #pragma unroll
    for (int q = 0; q < 8; q++) {
        double2 v = hp[q];
        u64 p0 = __double_as_longlong(v.x), p1 = __double_as_longlong(v.y);
        #pragma unroll
        for (int g = 0; g < 4; g++)
            acc[g] = ffma2(p0, w2[g][2 * q], acc[g]);
        #pragma unroll
        for (int g = 0; g < 4; g++)
            acc[g] = ffma2(p1, w2[g][2 * q + 1], acc[g]);
    }
}

__global__ void __launch_bounds__(128, 2) lstm_kernel(
    const float* __restrict__ x,      // [T, B, 1]
    const float* __restrict__ W_ih,   // [4H, 1]
    const float* __restrict__ W_hh,   // [4H, H]
    const float* __restrict__ b_ih,   // [4H]
    const float* __restrict__ b_hh,   // [4H]
    const float* __restrict__ W_out,  // [1, H]
    const float* __restrict__ b_out,  // [1]
    float* __restrict__ out,          // [T*B] outs, then [B*H] hT, then [B*H] cT
    int out_size)
{
    const int lane = threadIdx.x & 31;
    const int wid  = threadIdx.x >> 5;
    const int w    = blockIdx.x * 4 + wid;   // 0..1023
    const int b0   = 2 * w;                  // batch pair (b0, b0+1)

    // Per-lane weights, pre-scaled per gate (i,f,o: S_SIG; g: S_TNH).
    u64 w2[4][16];
    float wih[4], bias[4];
    #pragma unroll
    for (int g = 0; g < 4; g++) {
        const int row = g * 32 + lane;
        const float s = (g == 2) ? S_TNH : S_SIG;
        const float* wr = W_hh + row * HID;
        #pragma unroll
        for (int p = 0; p < 16; p++)
            w2[g][p] = pack2(wr[2 * p] * s, wr[2 * p + 1] * s);
        wih[g]  = W_ih[row] * s;
        bias[g] = (b_ih[row] + b_hh[row]) * s;
    }
    const float wout = W_out[lane];
    const float bout = b_out[0];

    // h staging: [warp][double-buffer][batch][hidden]
    __shared__ __align__(16) float sh[4][2][2][32];

    float h0 = 0.f, c0 = 0.f, h1 = 0.f, c1 = 0.f;
    float rpp0 = 0.f, rpp1 = 0.f;             // step t-1 output partials

    const float* xp = x + b0;
    float2 xv = *reinterpret_cast<const float2*>(xp);   // x(t)
    float* outp = out + b0;
    const int store_pred = (lane == 0);

    // prologue: h1(-1) = 0 for matvec_b1 at t=0; acc0 = gates_b0(0) (h=0 -> xgate only)
    sh[wid][0][1][lane] = 0.f;
    __syncwarp();
    u64 acc0[4];
    #pragma unroll
    for (int g = 0; g < 4; g++)
        acc0[g] = pack2(fmaf(xv.x, wih[g], bias[g]), 0.f);

    #pragma unroll 2
    for (int t = 0; t < T_STEPS; t++) {
        const int buf = t & 1;

        // ---- act_b0(t): acc0 -> h0(t); publish ----
        float rp0n;
        act_one(acc0, c0, h0, rp0n, wout);
        sh[wid][buf][0][lane] = h0;

        // ---- deferred reduction of step t-1 partials (overlaps matvec_b1) ----
        float r0 = rpp0, r1 = rpp1;
        #pragma unroll
        for (int off = 16; off; off >>= 1) {
            r0 += __shfl_xor_sync(0xffffffffu, r0, off);
            r1 += __shfl_xor_sync(0xffffffffu, r1, off);
        }

        // ---- matvec_b1(t): reads h1(t-1) from buf ----
        u64 acc1[4];
        #pragma unroll
        for (int g = 0; g < 4; g++)
            acc1[g] = pack2(fmaf(xv.y, wih[g], bias[g]), 0.f);
        matvec_one(acc1, sh[wid][buf][1], w2);

        // ---- store out[t-1] (placeholder at t==0, overwritten at t==1) ----
        stg64_pred(store_pred, outp, r0 + bout, r1 + bout);
        outp += (t > 0) ? BATCH : 0;

        __syncwarp();   // h0 STS visible to matvec_b0 below

        // ---- act_b1(t): acc1 -> h1(t); publish into next buffer ----
        float rp1n;
        act_one(acc1, c1, h1, rp1n, wout);
        sh[wid][buf ^ 1][1][lane] = h1;

        // ---- prefetch x(t+1) ----
        const float* xpn = (t < T_STEPS - 1) ? (xp + BATCH) : xp;
        float2 xnext = *reinterpret_cast<const float2*>(xpn);
        xp = xpn;

        // ---- matvec_b0(t+1): reads h0(t) just published (overlaps act_b1 tail) ----
        #pragma unroll
        for (int g = 0; g < 4; g++)
            acc0[g] = pack2(fmaf(xnext.x, wih[g], bias[g]), 0.f);
        matvec_one(acc0, sh[wid][buf][0], w2);

        __syncwarp();   // h1 STS visible to next iteration's matvec_b1

        rpp0 = rp0n;
        rpp1 = rp1n;
        xv = xnext;
    }

    // epilogue: reduce step T-1 partials -> out[T-1] (outp already at row T-1)
    {
        float r0 = rpp0, r1 = rpp1;
        #pragma unroll
        for (int off = 16; off; off >>= 1) {
            r0 += __shfl_xor_sync(0xffffffffu, r0, off);
            r1 += __shfl_xor_sync(0xffffffffu, r1, off);
        }
        stg64_pred(store_pred, outp, r0 + bout, r1 + bout);
    }

    // final state (hT, cT), each [B, H], appended after outs
    if (out_size >= T_STEPS * BATCH + 2 * BATCH * HID) {
        float* hT = out + (size_t)T_STEPS * BATCH;
        float* cT = hT + BATCH * HID;
        hT[(size_t)(b0 + 0) * HID + lane] = h0;
        hT[(size_t)(b0 + 1) * HID + lane] = h1;
        cT[(size_t)(b0 + 0) * HID + lane] = c0;
        cT[(size_t)(b0 + 1) * HID + lane] = c1;
    }
}

extern "C" void kernel_launch(void* const* d_in, const int* in_sizes, int n_in,
                              void* d_out, int out_size) {
    const float* x     = (const float*)d_in[0];
    const float* W_ih  = (const float*)d_in[1];
    const float* W_hh  = (const float*)d_in[2];
    const float* b_ih  = (const float*)d_in[3];
    const float* b_hh  = (const float*)d_in[4];
    const float* W_out = (const float*)d_in[5];
    const float* b_out = (const float*)d_in[6];
    float* out = (float*)d_out;

    // 1024 warps (2 skewed batch streams each) = 256 CTAs of 128 threads, 2 CTA/SM
    lstm_kernel<<<256, 128>>>(x, W_ih, W_hh, b_ih, b_hh, W_out, b_out, out, out_size);
}

// round 13
// speedup vs baseline: 1.3853x; 1.1699x over previous
#include <cuda_runtime.h>

#define T_STEPS 2048
#define BATCH   2048
#define HID     32

typedef unsigned long long u64;

#define S_SIG  (-1.4426950408889634f)   /* -log2(e)   */
#define S_TNH  (-2.8853900817779268f)   /* -2*log2(e) */

// ---- packed f32x2 helpers ----
__device__ __forceinline__ u64 ffma2(u64 a, u64 b, u64 c) {
    u64 d;
    asm("fma.rn.f32x2 %0, %1, %2, %3;" : "=l"(d) : "l"(a), "l"(b), "l"(c));
    return d;
}
__device__ __forceinline__ u64 pack2(float lo, float hi) {
    u64 d;
    asm("mov.b64 %0, {%1, %2};" : "=l"(d) : "f"(lo), "f"(hi));
    return d;
}
__device__ __forceinline__ void unpack2(u64 v, float& lo, float& hi) {
    asm("mov.b64 {%0, %1}, %2;" : "=f"(lo), "=f"(hi) : "l"(v));
}
__device__ __forceinline__ float ex2f(float x) {
    float y; asm("ex2.approx.f32 %0, %1;" : "=f"(y) : "f"(x)); return y;
}
__device__ __forceinline__ float rcpf(float x) {
    float y; asm("rcp.approx.f32 %0, %1;" : "=f"(y) : "f"(x)); return y;
}

// predicated STG.64, no BSSY/BSYNC
__device__ __forceinline__ void stg64_pred(int pred, float* p, float a, float b) {
    asm volatile("{\n\t"
                 ".reg .pred p;\n\t"
                 "setp.ne.u32 p, %0, 0;\n\t"
                 "@p st.global.v2.f32 [%1], {%2, %3};\n\t"
                 "}" :: "r"(pred), "l"(p), "f"(a), "f"(b) : "memory");
}

__global__ void __launch_bounds__(128, 2) lstm_kernel(
    const float* __restrict__ x,      // [T, B, 1]
    const float* __restrict__ W_ih,   // [4H, 1]
    const float* __restrict__ W_hh,   // [4H, H]
    const float* __restrict__ b_ih,   // [4H]
    const float* __restrict__ b_hh,   // [4H]
    const float* __restrict__ W_out,  // [1, H]
    const float* __restrict__ b_out,  // [1]
    float* __restrict__ out,          // [T*B] outs, then [B*H] hT, then [B*H] cT
    int out_size)
{
    const int lane = threadIdx.x & 31;
    const int wid  = threadIdx.x >> 5;
    const int w    = blockIdx.x * 4 + wid;   // 0..1023
    const int b0   = 2 * w;                  // batch pair (b0, b0+1)

    // Per-lane weights, pre-scaled per gate (i,f,o: S_SIG; g: S_TNH).
    u64 w2[4][16];
    float wih[4], bias[4];
    #pragma unroll
    for (int g = 0; g < 4; g++) {
        const int row = g * 32 + lane;
        const float s = (g == 2) ? S_TNH : S_SIG;
        const float* wr = W_hh + row * HID;
        #pragma unroll
        for (int p = 0; p < 16; p++)
            w2[g][p] = pack2(wr[2 * p] * s, wr[2 * p + 1] * s);
        wih[g]  = W_ih[row] * s;
        bias[g] = (b_ih[row] + b_hh[row]) * s;
    }
    const float wout = W_out[lane];
    const float bout = b_out[0];

    // ---- anti-phase stagger ----
    // Same-SM CTA pairs are (bid, bid+148) under the classic placement LUT, so
    // delaying the second wave's CTAs by ~half a loop period puts the two
    // co-resident warps of each SMSP in anti-phase: one warp's act/MUFU tail
    // overlaps the other's 128-FFMA2 matvec window. One-time cost ~384 cycles.
    if (blockIdx.x >= 148) {
        float d = 1.0f + (float)lane;
        #pragma unroll
        for (int i = 0; i < 96; i++)
            asm volatile("fma.rn.f32 %0, %0, 0f3F7FBE77, 0f38D1B717;" : "+f"(d));
        // keep d live without affecting results (condition is never true)
        if (__float_as_uint(d) == 0x7F800001u) out[out_size - 1] = d;
    }

    // h broadcast staging: [warp][double-buffer][batch][hidden]
    __shared__ __align__(16) float sh[4][2][2][32];

    float h0 = 0.f, c0 = 0.f, h1 = 0.f, c1 = 0.f;
    float rp0 = 0.f, rp1 = 0.f;               // deferred output partials

    const float* xp = x + b0;
    float2 xv = *reinterpret_cast<const float2*>(xp);
    float* outp = out + b0;
    const int store_pred = (lane == 0);

    #pragma unroll 2
    for (int t = 0; t < T_STEPS; t++) {
        const int buf = t & 1;
        // publish h(t-1)
        sh[wid][buf][0][lane] = h0;
        sh[wid][buf][1][lane] = h1;

        // clamped prefetch of next x
        const float* xpn = (t < T_STEPS - 1) ? (xp + BATCH) : xp;
        float2 xnext = *reinterpret_cast<const float2*>(xpn);
        xp = xpn;

        // init gate accumulators: lo = x*wih + bias, hi = 0
        u64 acc0[4], acc1[4];
        #pragma unroll
        for (int g = 0; g < 4; g++) {
            acc0[g] = pack2(fmaf(xv.x, wih[g], bias[g]), 0.0f);
            acc1[g] = pack2(fmaf(xv.y, wih[g], bias[g]), 0.0f);
        }

        __syncwarp();

        // deferred reduction of step t-1 output partials (hidden under matvec)
        float r0 = rp0, r1 = rp1;
        #pragma unroll
        for (int off = 16; off; off >>= 1) {
            r0 += __shfl_xor_sync(0xffffffffu, r0, off);
            r1 += __shfl_xor_sync(0xffffffffu, r1, off);
        }

        // recurrent matvec: 8 chains (2 batches x 4 gates), 128 FFMA2
        const double2* hp0 = reinterpret_cast<const double2*>(sh[wid][buf][0]);
        const double2* hp1 = reinterpret_cast<const double2*>(sh[wid][buf][1]);
        #pragma unroll
        for (int q = 0; q < 8; q++) {
            double2 v0 = hp0[q], v1 = hp1[q];
            u64 p00 = __double_as_longlong(v0.x), p01 = __double_as_longlong(v0.y);
            u64 p10 = __double_as_longlong(v1.x), p11 = __double_as_longlong(v1.y);
            #pragma unroll
            for (int g = 0; g < 4; g++) {
                acc0[g] = ffma2(p00, w2[g][2 * q], acc0[g]);
                acc1[g] = ffma2(p10, w2[g][2 * q], acc1[g]);
            }
            #pragma unroll
            for (int g = 0; g < 4; g++) {
                acc0[g] = ffma2(p01, w2[g][2 * q + 1], acc0[g]);
                acc1[g] = ffma2(p11, w2[g][2 * q + 1], acc1[g]);
            }
        }

        // store out[t-1]; at t==0 writes a placeholder to out[0], overwritten at t==1
        stg64_pred(store_pred, outp, r0 + bout, r1 + bout);
        outp += (t > 0) ? BATCH : 0;

        // ---- horizontal adds ----
        float vi0, vf0, vg0, vo0, vi1, vf1, vg1, vo1;
        {
            float lo, hi;
            unpack2(acc0[0], lo, hi); vi0 = lo + hi;
            unpack2(acc0[1], lo, hi); vf0 = lo + hi;
            unpack2(acc0[2], lo, hi); vg0 = lo + hi;
            unpack2(acc0[3], lo, hi); vo0 = lo + hi;
            unpack2(acc1[0], lo, hi); vi1 = lo + hi;
            unpack2(acc1[1], lo, hi); vf1 = lo + hi;
            unpack2(acc1[2], lo, hi); vg1 = lo + hi;
            unpack2(acc1[3], lo, hi); vo1 = lo + hi;
        }

        // ---- quad-shared-rcp gates, batch 0 ----
        float i0g, f0g, o0g, g0g;
        {
            float Ei = ex2f(vi0), Ef = ex2f(vf0), Eg = ex2f(vg0), Eo = ex2f(vo0);
            float Pi = 1.f + Ei, Pf = 1.f + Ef, Pg = 1.f + Eg, Po = 1.f + Eo;
            float Pif = Pi * Pf, Pgo = Pg * Po;
            float R = rcpf(Pif * Pgo);
            float PgoR = Pgo * R, PifR = Pif * R;
            i0g = Pf * PgoR; f0g = Pi * PgoR;
            o0g = PifR * Pg; g0g = fmaf(2.f, PifR * Po, -1.f);
        }
        // ---- quad-shared-rcp gates, batch 1 ----
        float i1g, f1g, o1g, g1g;
        {
            float Ei = ex2f(vi1), Ef = ex2f(vf1), Eg = ex2f(vg1), Eo = ex2f(vo1);
            float Pi = 1.f + Ei, Pf = 1.f + Ef, Pg = 1.f + Eg, Po = 1.f + Eo;
            float Pif = Pi * Pf, Pgo = Pg * Po;
            float R = rcpf(Pif * Pgo);
            float PgoR = Pgo * R, PifR = Pif * R;
            i1g = Pf * PgoR; f1g = Pi * PgoR;
            o1g = PifR * Pg; g1g = fmaf(2.f, PifR * Po, -1.f);
        }

        c0 = fmaf(f0g, c0, i0g * g0g);
        c1 = fmaf(f1g, c1, i1g * g1g);

        // ---- paired tanh(c): one rcp for both batches ----
        {
            float a0 = fminf(c0 * S_TNH, 63.f);
            float a1 = fminf(c1 * S_TNH, 63.f);
            float T0 = 1.f + ex2f(a0);
            float T1 = 1.f + ex2f(a1);
            float Rt = rcpf(T0 * T1);
            h0 = o0g * fmaf(2.f, T1 * Rt, -1.f);
            h1 = o1g * fmaf(2.f, T0 * Rt, -1.f);
        }

        rp0 = h0 * wout;
        rp1 = h1 * wout;

        xv = xnext;
    }

    // epilogue: reduce final step partials -> out[T-1] (outp already at row T-1)
    {
        float r0 = rp0, r1 = rp1;
        #pragma unroll
        for (int off = 16; off; off >>= 1) {
            r0 += __shfl_xor_sync(0xffffffffu, r0, off);
            r1 += __shfl_xor_sync(0xffffffffu, r1, off);
        }
        stg64_pred(store_pred, outp, r0 + bout, r1 + bout);
    }

    // final state (hT, cT), each [B, H], appended after outs
    if (out_size >= T_STEPS * BATCH + 2 * BATCH * HID) {
        float* hT = out + (size_t)T_STEPS * BATCH;
        float* cT = hT + BATCH * HID;
        hT[(size_t)(b0 + 0) * HID + lane] = h0;
        hT[(size_t)(b0 + 1) * HID + lane] = h1;
        cT[(size_t)(b0 + 0) * HID + lane] = c0;
        cT[(size_t)(b0 + 1) * HID + lane] = c1;
    }
}

extern "C" void kernel_launch(void* const* d_in, const int* in_sizes, int n_in,
                              void* d_out, int out_size) {
    const float* x     = (const float*)d_in[0];
    const float* W_ih  = (const float*)d_in[1];
    const float* W_hh  = (const float*)d_in[2];
    const float* b_ih  = (const float*)d_in[3];
    const float* b_hh  = (const float*)d_in[4];
    const float* W_out = (const float*)d_in[5];
    const float* b_out = (const float*)d_in[6];
    float* out = (float*)d_out;

    // 1024 warps (2 batch elems each) = 256 CTAs of 128 threads, 2 CTA/SM,
    // second-wave CTAs phase-staggered vs their SM partner.
    lstm_kernel<<<256, 128>>>(x, W_ih, W_hh, b_ih, b_hh, W_out, b_out, out, out_size);
}